// round 11
// baseline (speedup 1.0000x reference)
#include <cuda_runtime.h>
#include <cstdint>
#include <math.h>

#define B_   2
#define S_   2048
#define DIN  2048
#define H_   32
#define G_   8
#define R_   4
#define HD   64
#define DKV  512            // G_*HD
#define MROWS (B_*S_)       // 4096

// ---------------------------------------------------------------------------
// Device-global scratch (allocation-free rule)
// ---------------------------------------------------------------------------
__device__ float g_Q[(size_t)MROWS*DIN];    // dim-axis permuted within 8-groups
__device__ float g_K[(size_t)MROWS*DKV];    // dim-axis permuted within 8-groups
__device__ float g_V[(size_t)MROWS*DKV];    // natural
__device__ float g_ctx[(size_t)MROWS*DIN];  // natural
__device__ float g_xr [(size_t)MROWS*DIN];
__device__ float g_Wqr[(size_t)DIN*DIN];
__device__ float g_Wkr[(size_t)DKV*DIN];
__device__ float g_Wvr[(size_t)DKV*DIN];
__device__ float g_Wor[(size_t)DIN*DIN];

// ---------------------------------------------------------------------------
// helpers
// ---------------------------------------------------------------------------
__device__ __forceinline__ uint32_t smem_u32(const void* p) {
    uint32_t a;
    asm("{ .reg .u64 t; cvta.to.shared.u64 t, %1; cvt.u32.u64 %0, t; }" : "=r"(a) : "l"(p));
    return a;
}
__device__ __forceinline__ void cp_async16(uint32_t dst, const void* src) {
    asm volatile("cp.async.cg.shared.global [%0], [%1], 16;" :: "r"(dst), "l"(src) : "memory");
}
#define CP_COMMIT()  asm volatile("cp.async.commit_group;" ::: "memory")

__device__ __forceinline__ void mma_tf32(float* d, const float* a, const float* b) {
    asm volatile(
        "mma.sync.aligned.m16n8k8.row.col.f32.tf32.tf32.f32 "
        "{%0,%1,%2,%3}, {%4,%5,%6,%7}, {%8,%9}, {%0,%1,%2,%3};"
        : "+f"(d[0]), "+f"(d[1]), "+f"(d[2]), "+f"(d[3])
        : "r"(__float_as_uint(a[0])), "r"(__float_as_uint(a[1])),
          "r"(__float_as_uint(a[2])), "r"(__float_as_uint(a[3])),
          "r"(__float_as_uint(b[0])), "r"(__float_as_uint(b[1])));
}
__device__ __forceinline__ float tf32r(float x) {
    asm("cvt.rna.tf32.f32 %0, %0;" : "+f"(x));
    return x;
}
__device__ __forceinline__ float ex2(float x) {
    asm("ex2.approx.f32 %0, %0;" : "+f"(x));
    return x;
}
// within-8 permutation: logical k-index c -> storage position
__device__ __forceinline__ int kperm(int c) { return (c < 4) ? 2 * c : 2 * c - 7; }

// ---------------------------------------------------------------------------
// Round fp32 -> tf32 (rna), 4 float4 per thread for MLP
// ---------------------------------------------------------------------------
__global__ __launch_bounds__(256) void round_tf32(const float* __restrict__ in,
                                                  float* __restrict__ out, int n4) {
    int base = blockIdx.x * 1024 + threadIdx.x;
#pragma unroll
    for (int l = 0; l < 4; l++) {
        int i = base + l * 256;
        if (i < n4) {
            float4 v = *(const float4*)(in + (size_t)i * 4);
            v.x = tf32r(v.x); v.y = tf32r(v.y); v.z = tf32r(v.z); v.w = tf32r(v.w);
            *(float4*)(out + (size_t)i * 4) = v;
        }
    }
}

// ---------------------------------------------------------------------------
// tf32 mma.sync GEMM core
// ---------------------------------------------------------------------------
#define BK      32
#define NCH     (DIN / BK)          // 64
#define SROW    36
#define STAGEF  (2 * 128 * SROW)
#define SMEM_DYN (2 * STAGEF * 4)   // 73728 bytes

__device__ __forceinline__ void g_load(uint32_t sbase, int c, int tid,
                                       const float* __restrict__ A,
                                       const float* __restrict__ W,
                                       int bm, int bn) {
    const uint32_t sA = sbase + (uint32_t)(c & 1) * (STAGEF * 4);
    const uint32_t sB = sA + 128 * SROW * 4;
    const float* gA = A + (size_t)bm * DIN + c * BK;
    const float* gB = W + (size_t)bn * DIN + c * BK;
#pragma unroll
    for (int i = 0; i < 4; i++) {
        int idx = tid + i * 256;
        int r = idx >> 3, j = idx & 7;
        cp_async16(sA + r * (SROW * 4) + j * 16, gA + (size_t)r * DIN + j * 4);
    }
#pragma unroll
    for (int i = 0; i < 4; i++) {
        int idx = tid + i * 256;
        int r = idx >> 3, j = idx & 7;
        cp_async16(sB + r * (SROW * 4) + j * 16, gB + (size_t)r * DIN + j * 4);
    }
}

// mainloop shared by all gemm kernels; acc[4][4][4]
__device__ __forceinline__ void gemm_core(float* dsm, uint32_t sbase, int tid,
                                          const float* A, const float* W,
                                          int bm, int bn, float acc[4][4][4]) {
    const int lane = tid & 31;
    const int wid  = tid >> 5;
    const int wm   = wid & 1;
    const int wn   = wid >> 1;
    const int lr   = lane >> 2;
    const int lc   = lane & 3;

    g_load(sbase, 0, tid, A, W, bm, bn);
    CP_COMMIT();

    for (int c = 0; c < NCH; c++) {
        if (c + 1 < NCH) {
            g_load(sbase, c + 1, tid, A, W, bm, bn);
            CP_COMMIT();
            asm volatile("cp.async.wait_group 1;" ::: "memory");
        } else {
            asm volatile("cp.async.wait_group 0;" ::: "memory");
        }
        __syncthreads();

        const float* As = dsm + (c & 1) * STAGEF;
        const float* Bs = As + 128 * SROW;
#pragma unroll
        for (int ks = 0; ks < 4; ks++) {
            const int k0 = ks * 8;
            float af[4][4], bf[4][2];
#pragma unroll
            for (int mt = 0; mt < 4; mt++) {
                const float* ar = As + (wm * 64 + mt * 16 + lr) * SROW + k0 + lc;
                af[mt][0] = ar[0];
                af[mt][1] = ar[8 * SROW];
                af[mt][2] = ar[4];
                af[mt][3] = ar[8 * SROW + 4];
            }
#pragma unroll
            for (int nt = 0; nt < 4; nt++) {
                const float* br = Bs + (wn * 32 + nt * 8 + lr) * SROW + k0 + lc;
                bf[nt][0] = br[0];
                bf[nt][1] = br[4];
            }
#pragma unroll
            for (int mt = 0; mt < 4; mt++)
#pragma unroll
                for (int nt = 0; nt < 4; nt++)
                    mma_tf32(acc[mt][nt], af[mt], bf[nt]);
        }
        __syncthreads();
    }
}

// Q / O projections.  PERM: permute dim-axis within 8-groups on store.
template <bool PERM>
__global__ __launch_bounds__(256, 2) void gemm_tc(const float* __restrict__ A,
                                                  const float* __restrict__ W,
                                                  float* __restrict__ C, int ldc) {
    extern __shared__ float dsm[];
    const int tid  = threadIdx.x;
    const int lane = tid & 31;
    const int wid  = tid >> 5;
    const int wm   = wid & 1;
    const int wn   = wid >> 1;
    const int lr   = lane >> 2;
    const int lc   = lane & 3;
    const int bm   = blockIdx.y * 128;
    const int bn   = blockIdx.x * 128;

    float acc[4][4][4];
#pragma unroll
    for (int mt = 0; mt < 4; mt++)
#pragma unroll
        for (int nt = 0; nt < 4; nt++)
#pragma unroll
            for (int r = 0; r < 4; r++) acc[mt][nt][r] = 0.f;

    gemm_core(dsm, smem_u32(dsm), tid, A, W, bm, bn, acc);

    const int p0 = kperm(2 * lc), p1 = kperm(2 * lc + 1);
#pragma unroll
    for (int mt = 0; mt < 4; mt++) {
        const int row = bm + wm * 64 + mt * 16 + lr;
#pragma unroll
        for (int nt = 0; nt < 4; nt++) {
            const int cb = bn + wn * 32 + nt * 8;
            if (PERM) {
                C[(size_t)row * ldc + cb + p0]       = acc[mt][nt][0];
                C[(size_t)row * ldc + cb + p1]       = acc[mt][nt][1];
                C[(size_t)(row + 8) * ldc + cb + p0] = acc[mt][nt][2];
                C[(size_t)(row + 8) * ldc + cb + p1] = acc[mt][nt][3];
            } else {
                *(float2*)&C[(size_t)row * ldc + cb + 2 * lc] =
                    make_float2(acc[mt][nt][0], acc[mt][nt][1]);
                *(float2*)&C[(size_t)(row + 8) * ldc + cb + 2 * lc] =
                    make_float2(acc[mt][nt][2], acc[mt][nt][3]);
            }
        }
    }
}

// Fused K+V projections (z=0 -> K, z=1 -> V). Epilogue rounds to tf32,
// writes g_K (permuted) / g_V (natural) plus the KV caches [b,g,s,d].
__global__ __launch_bounds__(256, 2) void gemm_kv(const float* __restrict__ A,
                                                  const float* __restrict__ Wk,
                                                  const float* __restrict__ Wv,
                                                  float* __restrict__ Ko,
                                                  float* __restrict__ Vo,
                                                  float* __restrict__ keys,
                                                  float* __restrict__ vals) {
    extern __shared__ float dsm[];
    const int tid  = threadIdx.x;
    const int lane = tid & 31;
    const int wid  = tid >> 5;
    const int wm   = wid & 1;
    const int wn   = wid >> 1;
    const int lr   = lane >> 2;
    const int lc   = lane & 3;
    const int bm   = blockIdx.y * 128;
    const int bn   = blockIdx.x * 128;
    const bool isK = (blockIdx.z == 0);

    const float* W  = isK ? Wk : Wv;
    float* C   = isK ? Ko : Vo;
    float* Ckv = isK ? keys : vals;

    float acc[4][4][4];
#pragma unroll
    for (int mt = 0; mt < 4; mt++)
#pragma unroll
        for (int nt = 0; nt < 4; nt++)
#pragma unroll
            for (int r = 0; r < 4; r++) acc[mt][nt][r] = 0.f;

    gemm_core(dsm, smem_u32(dsm), tid, A, W, bm, bn, acc);

    const int p0 = kperm(2 * lc), p1 = kperm(2 * lc + 1);
#pragma unroll
    for (int mt = 0; mt < 4; mt++) {
        const int row = bm + wm * 64 + mt * 16 + lr;
#pragma unroll
        for (int nt = 0; nt < 4; nt++) {
            const int cb  = bn + wn * 32 + nt * 8;
            const int col = cb + 2 * lc;
            float v0 = tf32r(acc[mt][nt][0]), v1 = tf32r(acc[mt][nt][1]);
            float v2 = tf32r(acc[mt][nt][2]), v3 = tf32r(acc[mt][nt][3]);
            if (isK) {
                C[(size_t)row * DKV + cb + p0]       = v0;
                C[(size_t)row * DKV + cb + p1]       = v1;
                C[(size_t)(row + 8) * DKV + cb + p0] = v2;
                C[(size_t)(row + 8) * DKV + cb + p1] = v3;
            } else {
                *(float2*)&C[(size_t)row * DKV + col]       = make_float2(v0, v1);
                *(float2*)&C[(size_t)(row + 8) * DKV + col] = make_float2(v2, v3);
            }
            // cache layout [b, g, s, d]; row = b*S+s, col = g*64+d (natural)
            const int g = col >> 6;
            const int d = col & 63;
            {
                const int b0 = row >> 11, s0 = row & 2047;
                *(float2*)&Ckv[(((size_t)(b0 * G_ + g)) * S_ + s0) * HD + d] = make_float2(v0, v1);
                const int r2 = row + 8;
                const int b1 = r2 >> 11, s1 = r2 & 2047;
                *(float2*)&Ckv[(((size_t)(b1 * G_ + g)) * S_ + s1) * HD + d] = make_float2(v2, v3);
            }
        }
    }
}

// ---------------------------------------------------------------------------
// Tensor-core flash attention (causal, tf32 mma.sync, online softmax)
// CTA: 128 q-rows, 8 warps (16 rows each). kt tiles of 64 keys, single stage.
// Smem: Qs[128][68], Ps[128][68], Ks[64][68], Vs[64][72] = 105472 B.
// Q/K dim-axis and P key-axis stored k-permuted -> paired LDS.64 fragments.
// ---------------------------------------------------------------------------
#define QP 68
#define KP 68
#define VP 72
#define ATTN_SMEM ((128*QP + 128*QP + 64*KP + 64*VP) * 4)   // 105472

__global__ __launch_bounds__(256, 2) void attn_tc()
{
    extern __shared__ float sm[];
    float* Qs = sm;                       // 128*68
    float* Ps = Qs + 128 * QP;            // 128*68
    float* Ks = Ps + 128 * QP;            // 64*68
    float* Vs = Ks + 64 * KP;             // 64*72

    const int qt  = (int)gridDim.x - 1 - (int)blockIdx.x;   // big tiles first
    const int h   = blockIdx.y;
    const int b   = blockIdx.z;
    const int g   = h >> 2;
    const int tid = threadIdx.x;
    const int wid = tid >> 5;
    const int lane = tid & 31;
    const int lr  = lane >> 2;
    const int lc  = lane & 3;
    const int w16 = wid * 16;

    const uint32_t sKs = smem_u32(Ks);
    const uint32_t sVs = smem_u32(Vs);

    const float qscale = 0.125f * 1.44269504088896340736f;  // 1/sqrt(64)*log2(e)
    const int nkt = 2 * qt + 2;

    // ---- stage Q (scaled + tf32-rounded); g_Q already dim-permuted ----
#pragma unroll
    for (int i = 0; i < 8; i++) {
        int f  = tid + i * 256;
        int r  = f >> 4;
        int dc = (f & 15) * 4;
        float4 v = *(const float4*)&g_Q[(size_t)(b * S_ + qt * 128 + r) * DIN + h * HD + dc];
        v.x = tf32r(v.x * qscale); v.y = tf32r(v.y * qscale);
        v.z = tf32r(v.z * qscale); v.w = tf32r(v.w * qscale);
        *(float4*)&Qs[r * QP + dc] = v;
    }

    float o[8][4];
#pragma unroll
    for (int nt = 0; nt < 8; nt++)
#pragma unroll
        for (int r = 0; r < 4; r++) o[nt][r] = 0.f;
    float m0 = -1e30f, m1 = -1e30f, l0 = 0.f, l1 = 0.f;

    const int row0 = qt * 128 + w16 + lr;
    const int pp0 = kperm(2 * lc), pp1 = kperm(2 * lc + 1);

    for (int kt = 0; kt < nkt; kt++) {
        __syncthreads();    // prior tile's reads of Ks/Vs done (and Q staged)
        // ---- load K/V tile (pre-rounded tf32; K dim-permuted) ----
#pragma unroll
        for (int i = 0; i < 4; i++) {
            int f  = tid + i * 256;
            int r  = f >> 4;
            int dc = (f & 15) * 4;
            size_t src = (size_t)(b * S_ + kt * 64 + r) * DKV + g * HD + dc;
            cp_async16(sKs + (uint32_t)(r * KP + dc) * 4, &g_K[src]);
            cp_async16(sVs + (uint32_t)(r * VP + dc) * 4, &g_V[src]);
        }
        CP_COMMIT();
        asm volatile("cp.async.wait_group 0;" ::: "memory");
        __syncthreads();

        // ---- S = Q @ K^T (log2 domain), paired fragment loads ----
        float sc[8][4];
#pragma unroll
        for (int nt = 0; nt < 8; nt++)
#pragma unroll
            for (int r = 0; r < 4; r++) sc[nt][r] = 0.f;
#pragma unroll
        for (int ks = 0; ks < 8; ks++) {
            float2 a0 = *(float2*)&Qs[(w16 + lr) * QP + ks * 8 + 2 * lc];
            float2 a1 = *(float2*)&Qs[(w16 + lr + 8) * QP + ks * 8 + 2 * lc];
            float af[4] = {a0.x, a1.x, a0.y, a1.y};
#pragma unroll
            for (int nt = 0; nt < 8; nt++) {
                float2 bb = *(float2*)&Ks[(nt * 8 + lr) * KP + ks * 8 + 2 * lc];
                float bf[2] = {bb.x, bb.y};
                mma_tf32(sc[nt], af, bf);
            }
        }

        // ---- causal mask (keys are natural on the mma N axis) ----
        if (kt * 64 + 63 > row0) {
#pragma unroll
            for (int nt = 0; nt < 8; nt++) {
                int col = kt * 64 + nt * 8 + 2 * lc;
                if (col     > row0)     sc[nt][0] = -1e30f;
                if (col + 1 > row0)     sc[nt][1] = -1e30f;
                if (col     > row0 + 8) sc[nt][2] = -1e30f;
                if (col + 1 > row0 + 8) sc[nt][3] = -1e30f;
            }
        }

        // ---- online softmax (base-2 domain) ----
        float r0 = -1e30f, r1 = -1e30f;
#pragma unroll
        for (int nt = 0; nt < 8; nt++) {
            r0 = fmaxf(r0, fmaxf(sc[nt][0], sc[nt][1]));
            r1 = fmaxf(r1, fmaxf(sc[nt][2], sc[nt][3]));
        }
        r0 = fmaxf(r0, __shfl_xor_sync(0xffffffffu, r0, 1));
        r0 = fmaxf(r0, __shfl_xor_sync(0xffffffffu, r0, 2));
        r1 = fmaxf(r1, __shfl_xor_sync(0xffffffffu, r1, 1));
        r1 = fmaxf(r1, __shfl_xor_sync(0xffffffffu, r1, 2));
        float mn0 = fmaxf(m0, r0), mn1 = fmaxf(m1, r1);
        float a0 = ex2(m0 - mn0), a1 = ex2(m1 - mn1);
        m0 = mn0; m1 = mn1;

        float ps0 = 0.f, ps1 = 0.f;
#pragma unroll
        for (int nt = 0; nt < 8; nt++) {
            float p00 = tf32r(ex2(sc[nt][0] - mn0));
            float p01 = tf32r(ex2(sc[nt][1] - mn0));
            float p10 = tf32r(ex2(sc[nt][2] - mn1));
            float p11 = tf32r(ex2(sc[nt][3] - mn1));
            ps0 += p00 + p01;
            ps1 += p10 + p11;
            // store P with key-axis permuted within 8-groups
            Ps[(w16 + lr) * QP + nt * 8 + pp0]     = p00;
            Ps[(w16 + lr) * QP + nt * 8 + pp1]     = p01;
            Ps[(w16 + lr + 8) * QP + nt * 8 + pp0] = p10;
            Ps[(w16 + lr + 8) * QP + nt * 8 + pp1] = p11;
            o[nt][0] *= a0; o[nt][1] *= a0;
            o[nt][2] *= a1; o[nt][3] *= a1;
        }
        ps0 += __shfl_xor_sync(0xffffffffu, ps0, 1);
        ps0 += __shfl_xor_sync(0xffffffffu, ps0, 2);
        ps1 += __shfl_xor_sync(0xffffffffu, ps1, 1);
        ps1 += __shfl_xor_sync(0xffffffffu, ps1, 2);
        l0 = l0 * a0 + ps0;
        l1 = l1 * a1 + ps1;
        __syncwarp();   // P rows are per-warp private

        // ---- ctx += P @ V (P k-pairs adjacent; V rows natural) ----
#pragma unroll
        for (int ks = 0; ks < 8; ks++) {
            float2 pa0 = *(float2*)&Ps[(w16 + lr) * QP + ks * 8 + 2 * lc];
            float2 pa1 = *(float2*)&Ps[(w16 + lr + 8) * QP + ks * 8 + 2 * lc];
            float af[4] = {pa0.x, pa1.x, pa0.y, pa1.y};
#pragma unroll
            for (int nt = 0; nt < 8; nt++) {
                float bf[2];
                bf[0] = Vs[(ks * 8 + lc) * VP + nt * 8 + lr];
                bf[1] = Vs[(ks * 8 + lc + 4) * VP + nt * 8 + lr];
                mma_tf32(o[nt], af, bf);
            }
        }
    }

    // ---- normalize + tf32-round + write context (natural layout) ----
    const float i0 = 1.f / l0, i1 = 1.f / l1;
#pragma unroll
    for (int nt = 0; nt < 8; nt++) {
        size_t d0 = (size_t)(b * S_ + row0) * DIN + h * HD + nt * 8 + 2 * lc;
        size_t d1 = (size_t)(b * S_ + row0 + 8) * DIN + h * HD + nt * 8 + 2 * lc;
        *(float2*)&g_ctx[d0] = make_float2(tf32r(o[nt][0] * i0), tf32r(o[nt][1] * i0));
        *(float2*)&g_ctx[d1] = make_float2(tf32r(o[nt][2] * i1), tf32r(o[nt][3] * i1));
    }
}

// ---------------------------------------------------------------------------
extern "C" void kernel_launch(void* const* d_in, const int* in_sizes, int n_in,
                              void* d_out, int out_size)
{
    const float* x  = (const float*)d_in[0];
    const float* Wq = (const float*)d_in[1];
    const float* Wk = (const float*)d_in[2];
    const float* Wv = (const float*)d_in[3];
    const float* Wo = (const float*)d_in[4];

    float* out  = (float*)d_out;
    float* keys = out + (size_t)MROWS * DIN;
    float* vals = keys + (size_t)B_ * G_ * S_ * HD;

    float *q, *k, *v, *ctx, *xr, *wqr, *wkr, *wvr, *wor;
    cudaGetSymbolAddress((void**)&q,   g_Q);
    cudaGetSymbolAddress((void**)&k,   g_K);
    cudaGetSymbolAddress((void**)&v,   g_V);
    cudaGetSymbolAddress((void**)&ctx, g_ctx);
    cudaGetSymbolAddress((void**)&xr,  g_xr);
    cudaGetSymbolAddress((void**)&wqr, g_Wqr);
    cudaGetSymbolAddress((void**)&wkr, g_Wkr);
    cudaGetSymbolAddress((void**)&wvr, g_Wvr);
    cudaGetSymbolAddress((void**)&wor, g_Wor);

    cudaFuncSetAttribute(gemm_tc<true>,  cudaFuncAttributeMaxDynamicSharedMemorySize, SMEM_DYN);
    cudaFuncSetAttribute(gemm_tc<false>, cudaFuncAttributeMaxDynamicSharedMemorySize, SMEM_DYN);
    cudaFuncSetAttribute(gemm_kv, cudaFuncAttributeMaxDynamicSharedMemorySize, SMEM_DYN);
    cudaFuncSetAttribute(attn_tc, cudaFuncAttributeMaxDynamicSharedMemorySize, ATTN_SMEM);

    round_tf32<<<(MROWS*DIN/4 + 1023)/1024, 256>>>(x,  xr,  MROWS*DIN/4);
    round_tf32<<<(DIN*DIN/4   + 1023)/1024, 256>>>(Wq, wqr, DIN*DIN/4);
    round_tf32<<<(DKV*DIN/4   + 1023)/1024, 256>>>(Wk, wkr, DKV*DIN/4);
    round_tf32<<<(DKV*DIN/4   + 1023)/1024, 256>>>(Wv, wvr, DKV*DIN/4);
    round_tf32<<<(DIN*DIN/4   + 1023)/1024, 256>>>(Wo, wor, DIN*DIN/4);

    gemm_tc<true><<<dim3(DIN/128, MROWS/128), 256, SMEM_DYN>>>(xr, wqr, q, DIN);
    gemm_kv<<<dim3(DKV/128, MROWS/128, 2), 256, SMEM_DYN>>>(xr, wkr, wvr, k, v, keys, vals);

    attn_tc<<<dim3(S_/128, H_, B_), 256, ATTN_SMEM>>>();

    gemm_tc<false><<<dim3(DIN/128, MROWS/128), 256, SMEM_DYN>>>(ctx, wor, out, DIN);
}